// round 15
// baseline (speedup 1.0000x reference)
#include <cuda_runtime.h>
#include <math.h>

// Branchless prob-space q_posterior (K=2), 268 MB logical traffic (floor):
//  alpha = exp(la[t]); oma = exp(l1a[t]) = 1-alpha
//  Qh = alpha + oma/2 (x_t one-hot "hit"), Ql = 1e-30*alpha + oma/2 ("miss")
//  t>0 : ab = exp(lab[t-1]), c = 0.5*exp(l1ab[t-1])
//  t==0: ab = 1, c = 0   (f0=e0, f1=1-e0 -> posterior = renorm(x0*Q): exact)
//  w0 = (ab*e0+c)*Q0 ; w1 = (ab*(1-e0)+c)*Q1 ; out = log(w/(w0+w1))
// Final config: streaming loads issued BEFORE the param barrier (loads don't
// depend on params; scoreboard wait lands at first use), thread-0 smem params
// (no per-warp SHFL chain), .cs loads AND stores (best steady-state replay).

__global__ void __launch_bounds__(256, 8) qpost_kernel(const float* __restrict__ xt,
                                                       const float* __restrict__ x0,
                                                       float* __restrict__ out,
                                                       const int* __restrict__ t_raw,
                                                       const float* __restrict__ la,
                                                       const float* __restrict__ l1a,
                                                       const float* __restrict__ lab,
                                                       const float* __restrict__ l1ab) {
    __shared__ float4 sP;

    unsigned tid = blockIdx.x * 256u + threadIdx.x;
    size_t e = (size_t)tid << 3;                   // 8 spatial elems per thread
    unsigned b = (unsigned)(e >> 20);              // batch (uniform per block)
    size_t base = ((size_t)b << 21) + (e & (((size_t)1 << 20) - 1));
    const size_t cstr = (size_t)1 << 20;           // class stride

    // ---- front-batched streaming loads FIRST (MLP=4, independent of params) ----
    float4 xtA = __ldcs((const float4*)(xt + base));
    float4 xtB = __ldcs((const float4*)(xt + base + 4));
    float4 x0A = __ldcs((const float4*)(x0 + base));
    float4 x0B = __ldcs((const float4*)(x0 + base + 4));

    // ---- thread-0 params -> smem (barrier waits on arrival, not on loads) ----
    if (threadIdx.x == 0) {
        // int64-vs-int32 sniff (t in [0,1000); int64 LE high words are 0)
        int hw = t_raw[1] | t_raw[3] | t_raw[5] | t_raw[7];
        int t = (hw == 0) ? t_raw[2 * b] : t_raw[b];
        float alpha = __expf(la[t]);
        float oma   = __expf(l1a[t]);              // 1 - alpha (+1e-40)
        float Qh = fmaf(0.5f, oma, alpha);
        float Ql = fmaf(0.5f, oma, 1e-30f * alpha);
        float ab, c;
        if (t == 0) { ab = 1.0f; c = 0.0f; }       // exact t==0 unification
        else        { ab = __expf(lab[t - 1]); c = 0.5f * __expf(l1ab[t - 1]); }
        sP = make_float4(ab, c, Qh, Ql);
    }
    __syncthreads();

    float4 P  = sP;
    float ab  = P.x, c = P.y, Qh = P.z, Ql = P.w;
    float abc = ab + c;

    // ---- compute + store per quad (short live ranges, regs <= 32) ----
    #pragma unroll
    for (int h = 0; h < 2; h++) {
        float4 xq = h ? xtB : xtA;
        float4 pq = h ? x0B : x0A;
        float4 o0, o1;
        #pragma unroll
        for (int k = 0; k < 4; k++) {
            float e0 = __expf(((const float*)&pq)[k]);   // exp(x01) = 1-e0 (K=2)
            float f0 = fmaf(ab, e0, c);
            float f1 = fmaf(-ab, e0, abc);               // ab*(1-e0)+c
            bool hi = (((const float*)&xq)[k] > -1.0f);  // one-hot hit on class 0?
            float w0 = f0 * (hi ? Qh : Ql);
            float w1 = f1 * (hi ? Ql : Qh);
            float r = __fdividef(1.0f, w0 + w1);
            ((float*)&o0)[k] = __logf(w0 * r);
            ((float*)&o1)[k] = __logf(w1 * r);
        }
        __stcs((float4*)(out + base + 4 * h),        o0);
        __stcs((float4*)(out + base + cstr + 4 * h), o1);
    }
}

extern "C" void kernel_launch(void* const* d_in, const int* in_sizes, int n_in,
                              void* d_out, int out_size) {
    const float* log_x_t = (const float*)d_in[0];
    const float* log_x_0 = (const float*)d_in[1];
    const float* la      = (const float*)d_in[2];
    const float* l1a     = (const float*)d_in[3];
    const float* lab     = (const float*)d_in[4];
    const float* l1ab    = (const float*)d_in[5];
    const int*   t_raw   = (const int*)d_in[6];

    // 16 * 2^20 spatial / 8 per thread = 2,097,152 threads = 8192 blocks
    qpost_kernel<<<8192, 256>>>(log_x_t, log_x_0, (float*)d_out,
                                t_raw, la, l1a, lab, l1ab);
}

// round 16
// speedup vs baseline: 1.0516x; 1.0516x over previous
#include <cuda_runtime.h>
#include <math.h>

// Branchless prob-space q_posterior (K=2), 268 MB logical traffic (floor):
//  alpha = exp(la[t]); oma = exp(l1a[t]) = 1-alpha
//  Qh = alpha + oma/2 (x_t one-hot "hit"), Ql = 1e-30*alpha + oma/2 ("miss")
//  t>0 : ab = exp(lab[t-1]), c = 0.5*exp(l1ab[t-1])
//  t==0: ab = 1, c = 0   (f0=e0, f1=1-e0 -> posterior = renorm(x0*Q): exact)
//  w0 = (ab*e0+c)*Q0 ; w1 = (ab*(1-e0)+c)*Q1 ; out = log(w/(w0+w1))
// R16: warp-interleaved 8-elem/thread layout — each warp owns 256 contiguous
// elems; lane L handles [4L,4L+4) and [128+4L,128+4L+4). Every LDG/STG.128 is
// fully coalesced (4 whole 128B lines/instr), unlike the tid<<3 layout whose
// wavefronts were 50% utilized. Params: thread-0 -> smem, barrier BEFORE loads
// (R5 ordering, measured best). .cs loads and stores.

__global__ void __launch_bounds__(256, 8) qpost_kernel(const float* __restrict__ xt,
                                                       const float* __restrict__ x0,
                                                       float* __restrict__ out,
                                                       const int* __restrict__ t_raw,
                                                       const float* __restrict__ la,
                                                       const float* __restrict__ l1a,
                                                       const float* __restrict__ lab,
                                                       const float* __restrict__ l1ab) {
    __shared__ float4 sP;

    // block covers 2048 contiguous spatial elems -> batch uniform per block
    unsigned blk_elem_hi = blockIdx.x >> 9;        // (blockIdx.x*2048)>>20
    if (threadIdx.x == 0) {
        // int64-vs-int32 sniff (t in [0,1000); int64 LE high words are 0)
        int hw = t_raw[1] | t_raw[3] | t_raw[5] | t_raw[7];
        int t = (hw == 0) ? t_raw[2 * blk_elem_hi] : t_raw[blk_elem_hi];
        float alpha = __expf(la[t]);
        float oma   = __expf(l1a[t]);              // 1 - alpha (+1e-40)
        float Qh = fmaf(0.5f, oma, alpha);
        float Ql = fmaf(0.5f, oma, 1e-30f * alpha);
        float ab, c;
        if (t == 0) { ab = 1.0f; c = 0.0f; }       // exact t==0 unification
        else        { ab = __expf(lab[t - 1]); c = 0.5f * __expf(l1ab[t - 1]); }
        sP = make_float4(ab, c, Qh, Ql);
    }
    __syncthreads();

    // warp-interleaved addressing: warp owns 256 contiguous elems
    unsigned w = (blockIdx.x * 256u + threadIdx.x) >> 5;   // global warp id
    unsigned L = threadIdx.x & 31;
    size_t e0 = ((size_t)w << 8) + 4u * L;         // chunk A elem index
    unsigned b = (unsigned)(e0 >> 20);             // batch
    size_t inb = e0 & (((size_t)1 << 20) - 1);
    size_t baseA = ((size_t)b << 21) + inb;        // class-0 addr, chunk A
    size_t baseB = baseA + 128;                    // chunk B (same batch: 2048|block)
    const size_t cstr = (size_t)1 << 20;           // class stride

    // ---- front-batched streaming loads (MLP=4, fully coalesced) ----
    float4 xtA = __ldcs((const float4*)(xt + baseA));
    float4 xtB = __ldcs((const float4*)(xt + baseB));
    float4 x0A = __ldcs((const float4*)(x0 + baseA));
    float4 x0B = __ldcs((const float4*)(x0 + baseB));

    float4 P  = sP;
    float ab  = P.x, c = P.y, Qh = P.z, Ql = P.w;
    float abc = ab + c;

    // ---- compute + store per chunk (short live ranges, regs <= 32) ----
    #pragma unroll
    for (int h = 0; h < 2; h++) {
        float4 xq = h ? xtB : xtA;
        float4 pq = h ? x0B : x0A;
        size_t bs = h ? baseB : baseA;
        float4 o0, o1;
        #pragma unroll
        for (int k = 0; k < 4; k++) {
            float e0f = __expf(((const float*)&pq)[k]);  // exp(x01) = 1-e0 (K=2)
            float f0 = fmaf(ab, e0f, c);
            float f1 = fmaf(-ab, e0f, abc);              // ab*(1-e0)+c
            bool hi = (((const float*)&xq)[k] > -1.0f);  // one-hot hit on class 0?
            float w0 = f0 * (hi ? Qh : Ql);
            float w1 = f1 * (hi ? Ql : Qh);
            float r = __fdividef(1.0f, w0 + w1);
            ((float*)&o0)[k] = __logf(w0 * r);
            ((float*)&o1)[k] = __logf(w1 * r);
        }
        __stcs((float4*)(out + bs),        o0);
        __stcs((float4*)(out + bs + cstr), o1);
    }
}

extern "C" void kernel_launch(void* const* d_in, const int* in_sizes, int n_in,
                              void* d_out, int out_size) {
    const float* log_x_t = (const float*)d_in[0];
    const float* log_x_0 = (const float*)d_in[1];
    const float* la      = (const float*)d_in[2];
    const float* l1a     = (const float*)d_in[3];
    const float* lab     = (const float*)d_in[4];
    const float* l1ab    = (const float*)d_in[5];
    const int*   t_raw   = (const int*)d_in[6];

    // 16 * 2^20 spatial / 8 per thread = 2,097,152 threads = 8192 blocks
    qpost_kernel<<<8192, 256>>>(log_x_t, log_x_0, (float*)d_out,
                                t_raw, la, l1a, lab, l1ab);
}